// round 6
// baseline (speedup 1.0000x reference)
#include <cuda_runtime.h>
#include <cuda_bf16.h>

// Per-net precomputed contribution: c[net] = deg>1 ? max(w,1)/(deg-1) : 0
// Static device scratch (no allocation allowed). N_NETS = 2,000,000 fixed.
#define MAX_NETS 2000000
__device__ float g_cnet[MAX_NETS];

__global__ void net_contrib_kernel(const float* __restrict__ net_weights,
                                   const int*   __restrict__ flat_net2pin,
                                   int n_nets) {
    int n = blockIdx.x * blockDim.x + threadIdx.x;
    if (n >= n_nets) return;
    int s = __ldg(flat_net2pin + n);
    int e = __ldg(flat_net2pin + n + 1);
    int deg = e - s;
    float w = fmaxf(__ldg(net_weights + n), 1.0f);
    g_cnet[n] = (deg > 1) ? (w / (float)(deg - 1)) : 0.0f;
}

__global__ void node_sum_kernel(const int* __restrict__ n2p_start,
                                const int* __restrict__ n2p,
                                const int* __restrict__ pin2net,
                                const int* __restrict__ movable_ptr,
                                int movable_const,
                                float* __restrict__ out,
                                int num_nodes) {
    int i = blockIdx.x * blockDim.x + threadIdx.x;
    if (i >= num_nodes) return;
    int movable = movable_ptr ? __ldg(movable_ptr) : movable_const;
    if (i >= movable) { out[i] = 0.0f; return; }

    int s = __ldg(n2p_start + i);
    int e = __ldg(n2p_start + i + 1);
    float acc = 0.0f;

    if ((e - s) == 4 && (s & 3) == 0) {
        // Fast path: constant degree 4, 16B-aligned slot range.
        int4 p = *reinterpret_cast<const int4*>(n2p + s);
        int n0 = __ldg(pin2net + p.x);
        int n1 = __ldg(pin2net + p.y);
        int n2 = __ldg(pin2net + p.z);
        int n3 = __ldg(pin2net + p.w);
        acc = (g_cnet[n0] + g_cnet[n1]) + (g_cnet[n2] + g_cnet[n3]);
    } else {
        // General CSR fallback.
        for (int j = s; j < e; ++j) {
            int p = __ldg(n2p + j);
            int n = __ldg(pin2net + p);
            acc += g_cnet[n];
        }
    }
    out[i] = acc;
}

extern "C" void kernel_launch(void* const* d_in, const int* in_sizes, int n_in,
                              void* d_out, int out_size) {
    // metadata order:
    // 0: net_weights        f32 [N_NETS]
    // 1: flat_node2pin_start i32 [N_NODES+1]
    // 2: flat_node2pin      i32 [N_PINS]
    // 3: pin2net_map        i32 [N_PINS]
    // 4: flat_net2pin       i32 [N_NETS+1]
    // 5: num_movable_nodes  scalar (if present as a buffer)
    const float* net_weights = (const float*)d_in[0];
    const int*   n2p_start   = (const int*)d_in[1];
    const int*   n2p         = (const int*)d_in[2];
    const int*   pin2net     = (const int*)d_in[3];
    const int*   net2pin     = (const int*)d_in[4];
    const int*   movable_ptr = (n_in >= 6) ? (const int*)d_in[5] : nullptr;

    int n_nets    = in_sizes[4] - 1;
    int num_nodes = in_sizes[1] - 1;
    if (n_nets > MAX_NETS) n_nets = MAX_NETS;

    const int TPB = 256;
    net_contrib_kernel<<<(n_nets + TPB - 1) / TPB, TPB>>>(net_weights, net2pin, n_nets);
    node_sum_kernel<<<(num_nodes + TPB - 1) / TPB, TPB>>>(
        n2p_start, n2p, pin2net, movable_ptr, 1800000,
        (float*)d_out, num_nodes);
}

// round 7
// speedup vs baseline: 1.0624x; 1.0624x over previous
#include <cuda_runtime.h>
#include <cuda_bf16.h>

// ---------------------------------------------------------------------------
// PrecondWL: out[node] = sum over node's pins of clamp(w[net],1)/(deg[net]-1)
// (deg>1 only), movable nodes only.
//
// Phase 1: cnet[n] = deg>1 ? max(w,1)/(deg-1) : 0        (streaming, vec4)
// Phase 2: out[i]  = sum_{p in pins(i)} cnet[pin2net[p]] (16M divergent gathers,
//          L1tex wavefront-rate bound ~= 1 wf/cyc/SM -> this IS the floor)
// Single persistent kernel with a sense-reversing grid barrier between phases.
// ---------------------------------------------------------------------------

#define N_NETS_MAX 2000000
__device__ float    g_cnet[N_NETS_MAX + 4];
__device__ unsigned g_bar_count = 0;
__device__ unsigned g_bar_sense = 0;

__global__ void __launch_bounds__(256)
precond_fused_kernel(const float* __restrict__ net_weights,
                     const int*   __restrict__ net2pin,      // starts, n_nets+1
                     const int*   __restrict__ n2p_start,    // starts, num_nodes+1
                     const int*   __restrict__ n2p,          // node->pin flat (perm)
                     const int*   __restrict__ pin2net,
                     const int*   __restrict__ movable_ptr,  // may be null
                     int movable_const,
                     float* __restrict__ out,
                     int n_nets, int num_nodes, int nblocks)
{
    const int tid      = blockIdx.x * blockDim.x + threadIdx.x;
    const int nthreads = nblocks * blockDim.x;

    // ---------------- Phase 1: per-net contribution (vectorized x4) --------
    const int nq = n_nets >> 2;
    for (int q = tid; q < nq; q += nthreads) {
        int4   s4  = __ldcs(reinterpret_cast<const int4*>(net2pin) + q);
        int    s4e = __ldcs(net2pin + 4 * q + 4);
        float4 w4  = __ldcs(reinterpret_cast<const float4*>(net_weights) + q);
        int d0 = s4.y - s4.x;
        int d1 = s4.z - s4.y;
        int d2 = s4.w - s4.z;
        int d3 = s4e  - s4.w;
        float4 c;
        c.x = (d0 > 1) ? fmaxf(w4.x, 1.0f) / (float)(d0 - 1) : 0.0f;
        c.y = (d1 > 1) ? fmaxf(w4.y, 1.0f) / (float)(d1 - 1) : 0.0f;
        c.z = (d2 > 1) ? fmaxf(w4.z, 1.0f) / (float)(d2 - 1) : 0.0f;
        c.w = (d3 > 1) ? fmaxf(w4.w, 1.0f) / (float)(d3 - 1) : 0.0f;
        *(reinterpret_cast<float4*>(g_cnet) + q) = c;
    }
    for (int n = (nq << 2) + tid; n < n_nets; n += nthreads) {  // generic tail
        int s = __ldcs(net2pin + n);
        int e = __ldcs(net2pin + n + 1);
        int d = e - s;
        float w = fmaxf(__ldcs(net_weights + n), 1.0f);
        g_cnet[n] = (d > 1) ? (w / (float)(d - 1)) : 0.0f;
    }

    // ---------------- Grid barrier (sense-reversing, replay-safe) ----------
    __syncthreads();
    if (threadIdx.x == 0) {
        __threadfence();  // publish this block's cnet writes
        unsigned oldsense = *((volatile unsigned*)&g_bar_sense);
        unsigned arrived  = atomicAdd(&g_bar_count, 1u);
        if (arrived == (unsigned)nblocks - 1u) {
            g_bar_count = 0;                      // reset for next replay
            __threadfence();
            *((volatile unsigned*)&g_bar_sense) = oldsense ^ 1u;  // release
        } else {
            while (*((volatile unsigned*)&g_bar_sense) == oldsense) {
                __nanosleep(64);
            }
        }
        __threadfence();  // acquire
    }
    __syncthreads();

    // ---------------- Phase 2: per-node gather-sum -------------------------
    const int movable = movable_ptr ? __ldg(movable_ptr) : movable_const;

    for (int i = tid; i < num_nodes; i += nthreads) {
        int s = __ldcs(n2p_start + i);
        int e = __ldcs(n2p_start + i + 1);
        float r = 0.0f;
        if (i < movable) {
            if ((e - s) == 4 && (s & 3) == 0) {
                // Fast path: degree-4, 16B-aligned slot range (this dataset).
                int4 p = __ldcs(reinterpret_cast<const int4*>(n2p + s));
                int a = __ldcg(pin2net + p.x);   // L2-only: no L1 reuse here
                int b = __ldcg(pin2net + p.y);
                int c = __ldcg(pin2net + p.z);
                int d = __ldcg(pin2net + p.w);
                // cnet gathers keep default L1 caching (small, sole L1 tenant)
                r = (__ldg(g_cnet + a) + __ldg(g_cnet + b)) +
                    (__ldg(g_cnet + c) + __ldg(g_cnet + d));
            } else {
                for (int j = s; j < e; ++j) {
                    int p = __ldcs(n2p + j);
                    int n = __ldcg(pin2net + p);
                    r += __ldg(g_cnet + n);
                }
            }
        }
        out[i] = r;  // d_out is poisoned: every element must be written
    }
}

extern "C" void kernel_launch(void* const* d_in, const int* in_sizes, int n_in,
                              void* d_out, int out_size) {
    // metadata order:
    // 0: net_weights         f32 [N_NETS]
    // 1: flat_node2pin_start i32 [N_NODES+1]
    // 2: flat_node2pin       i32 [N_PINS]
    // 3: pin2net_map         i32 [N_PINS]
    // 4: flat_net2pin        i32 [N_NETS+1]
    // 5: num_movable_nodes   scalar buffer (if present)
    const float* net_weights = (const float*)d_in[0];
    const int*   n2p_start   = (const int*)d_in[1];
    const int*   n2p         = (const int*)d_in[2];
    const int*   pin2net     = (const int*)d_in[3];
    const int*   net2pin     = (const int*)d_in[4];
    const int*   movable_ptr = (n_in >= 6) ? (const int*)d_in[5] : nullptr;

    int n_nets    = in_sizes[4] - 1;
    int num_nodes = in_sizes[1] - 1;
    if (n_nets > N_NETS_MAX) n_nets = N_NETS_MAX;

    const int TPB = 256;

    // Exact-residency grid so the device barrier cannot deadlock.
    int dev = 0;
    cudaGetDevice(&dev);
    int sms = 148;
    cudaDeviceGetAttribute(&sms, cudaDevAttrMultiProcessorCount, dev);
    int bpm = 1;
    cudaOccupancyMaxActiveBlocksPerMultiprocessor(&bpm, precond_fused_kernel, TPB, 0);
    if (bpm < 1) bpm = 1;
    int grid = sms * bpm;

    precond_fused_kernel<<<grid, TPB>>>(
        net_weights, net2pin, n2p_start, n2p, pin2net,
        movable_ptr, 1800000, (float*)d_out,
        n_nets, num_nodes, grid);
}

// round 8
// speedup vs baseline: 1.0645x; 1.0020x over previous
#include <cuda_runtime.h>
#include <cuda_bf16.h>

// ---------------------------------------------------------------------------
// PrecondWL: out[node] = sum over node's pins of clamp(w[net],1)/(deg[net]-1)
// (deg>1 only), movable nodes only.
//
// Phase 0 (no deps): out[i] = 0 for fixed nodes (overlaps phase 1).
// Phase 1: cnet[n] = deg>1 ? max(w,1)/(deg-1) : 0        (streaming, vec4)
// Phase 2: out[i]  = sum_{p in pins(i)} cnet[pin2net[p]] (16M divergent gathers
//          -> L1tex wavefront-rate bound; this is the floor)
// Single persistent kernel, sense-reversing grid barrier between phases.
// ---------------------------------------------------------------------------

#define N_NETS_MAX 2000000
__device__ float    g_cnet[N_NETS_MAX + 4];
__device__ unsigned g_bar_count = 0;
__device__ unsigned g_bar_sense = 0;

__global__ void __launch_bounds__(256, 8)   // force <=32 regs -> 2048 thr/SM
precond_fused_kernel(const float* __restrict__ net_weights,
                     const int*   __restrict__ net2pin,      // starts, n_nets+1
                     const int*   __restrict__ n2p_start,    // starts, num_nodes+1
                     const int*   __restrict__ n2p,          // node->pin flat (perm)
                     const int*   __restrict__ pin2net,
                     const int*   __restrict__ movable_ptr,  // may be null
                     int movable_const,
                     float* __restrict__ out,
                     int n_nets, int num_nodes, int nblocks)
{
    const int tid      = blockIdx.x * blockDim.x + threadIdx.x;
    const int nthreads = nblocks * blockDim.x;
    const int movable  = movable_ptr ? __ldg(movable_ptr) : movable_const;

    // ---------------- Phase 0: fixed-node zeros (no cnet dependency) -------
    for (int i = movable + tid; i < num_nodes; i += nthreads)
        out[i] = 0.0f;

    // ---------------- Phase 1: per-net contribution (vectorized x4) --------
    const int nq = n_nets >> 2;
    for (int q = tid; q < nq; q += nthreads) {
        int4   s4  = __ldcs(reinterpret_cast<const int4*>(net2pin) + q);
        int    s4e = __ldcs(net2pin + 4 * q + 4);
        float4 w4  = __ldcs(reinterpret_cast<const float4*>(net_weights) + q);
        int d0 = s4.y - s4.x;
        int d1 = s4.z - s4.y;
        int d2 = s4.w - s4.z;
        int d3 = s4e  - s4.w;
        float4 c;
        c.x = (d0 > 1) ? fmaxf(w4.x, 1.0f) / (float)(d0 - 1) : 0.0f;
        c.y = (d1 > 1) ? fmaxf(w4.y, 1.0f) / (float)(d1 - 1) : 0.0f;
        c.z = (d2 > 1) ? fmaxf(w4.z, 1.0f) / (float)(d2 - 1) : 0.0f;
        c.w = (d3 > 1) ? fmaxf(w4.w, 1.0f) / (float)(d3 - 1) : 0.0f;
        *(reinterpret_cast<float4*>(g_cnet) + q) = c;
    }
    for (int n = (nq << 2) + tid; n < n_nets; n += nthreads) {  // generic tail
        int s = __ldcs(net2pin + n);
        int e = __ldcs(net2pin + n + 1);
        int d = e - s;
        float w = fmaxf(__ldcs(net_weights + n), 1.0f);
        g_cnet[n] = (d > 1) ? (w / (float)(d - 1)) : 0.0f;
    }

    // ---------------- Grid barrier (sense-reversing, replay-safe) ----------
    __syncthreads();
    if (threadIdx.x == 0) {
        __threadfence();  // publish this block's cnet writes
        unsigned oldsense = *((volatile unsigned*)&g_bar_sense);
        unsigned arrived  = atomicAdd(&g_bar_count, 1u);
        if (arrived == (unsigned)nblocks - 1u) {
            g_bar_count = 0;                      // reset for next replay
            __threadfence();
            *((volatile unsigned*)&g_bar_sense) = oldsense ^ 1u;  // release
        } else {
            while (*((volatile unsigned*)&g_bar_sense) == oldsense) {
                __nanosleep(64);
            }
        }
        __threadfence();  // acquire
    }
    __syncthreads();

    // ---------------- Phase 2: per-node gather-sum (movable only) ----------
    for (int i = tid; i < movable; i += nthreads) {
        int s, e;
        if ((i & 1) == 0) {
            // starts[i] is 8B-aligned for even i: one int2 load gets (s, e).
            int2 se = __ldcs(reinterpret_cast<const int2*>(n2p_start + i));
            s = se.x; e = se.y;
        } else {
            s = __ldcs(n2p_start + i);
            e = __ldcs(n2p_start + i + 1);
        }
        float r;
        if ((e - s) == 4 && (s & 3) == 0) {
            // Fast path: degree-4, 16B-aligned slot range (this dataset).
            int4 p = __ldcs(reinterpret_cast<const int4*>(n2p + s));
            int a = __ldcg(pin2net + p.x);   // L2-only: no L1 reuse
            int b = __ldcg(pin2net + p.y);
            int c = __ldcg(pin2net + p.z);
            int d = __ldcg(pin2net + p.w);
            // cnet gathers keep default caching (sole L1 tenant)
            r = (__ldg(g_cnet + a) + __ldg(g_cnet + b)) +
                (__ldg(g_cnet + c) + __ldg(g_cnet + d));
        } else {
            r = 0.0f;
            for (int j = s; j < e; ++j) {
                int p = __ldcs(n2p + j);
                int n = __ldcg(pin2net + p);
                r += __ldg(g_cnet + n);
            }
        }
        out[i] = r;  // d_out is poisoned: every movable element written here
    }
}

extern "C" void kernel_launch(void* const* d_in, const int* in_sizes, int n_in,
                              void* d_out, int out_size) {
    // metadata order:
    // 0: net_weights         f32 [N_NETS]
    // 1: flat_node2pin_start i32 [N_NODES+1]
    // 2: flat_node2pin       i32 [N_PINS]
    // 3: pin2net_map         i32 [N_PINS]
    // 4: flat_net2pin        i32 [N_NETS+1]
    // 5: num_movable_nodes   scalar buffer (if present)
    const float* net_weights = (const float*)d_in[0];
    const int*   n2p_start   = (const int*)d_in[1];
    const int*   n2p         = (const int*)d_in[2];
    const int*   pin2net     = (const int*)d_in[3];
    const int*   net2pin     = (const int*)d_in[4];
    const int*   movable_ptr = (n_in >= 6) ? (const int*)d_in[5] : nullptr;

    int n_nets    = in_sizes[4] - 1;
    int num_nodes = in_sizes[1] - 1;
    if (n_nets > N_NETS_MAX) n_nets = N_NETS_MAX;

    const int TPB = 256;

    // Exact-residency grid so the device barrier cannot deadlock.
    int dev = 0;
    cudaGetDevice(&dev);
    int sms = 148;
    cudaDeviceGetAttribute(&sms, cudaDevAttrMultiProcessorCount, dev);
    int bpm = 1;
    cudaOccupancyMaxActiveBlocksPerMultiprocessor(&bpm, precond_fused_kernel, TPB, 0);
    if (bpm < 1) bpm = 1;
    int grid = sms * bpm;

    precond_fused_kernel<<<grid, TPB>>>(
        net_weights, net2pin, n2p_start, n2p, pin2net,
        movable_ptr, 1800000, (float*)d_out,
        n_nets, num_nodes, grid);
}